// round 2
// baseline (speedup 1.0000x reference)
#include <cuda_runtime.h>
#include <math.h>

#define K_CTX 64
#define D_DIM 128
#define C_CAND 256
#define DS 200
#define EPS 1e-8f

// Scratch (device globals; no allocation allowed)
__device__ float g_A[K_CTX * D_DIM];
__device__ float g_AM[K_CTX * D_DIM];

// ---------------------------------------------------------------------------
// Kernel 1: gather A = table[t1_ctx] and compute AM = A @ att_mat
// grid = 64 (one block per context row k), block = 128 threads (one per d)
// NOTE: indices are int32 (JAX downgrades int64 without x64 mode).
// ---------------------------------------------------------------------------
__global__ void prep_kernel(const float* __restrict__ table,
                            const float* __restrict__ att_mat,
                            const int* __restrict__ t1_ctx) {
    int k = blockIdx.x;
    int d = threadIdx.x;
    __shared__ float arow[D_DIM];

    long long r = (long long)t1_ctx[k];
    float a = table[r * D_DIM + d];
    arow[d] = a;
    g_A[k * D_DIM + d] = a;
    __syncthreads();

    float acc = 0.f;
#pragma unroll 8
    for (int e = 0; e < D_DIM; e++)
        acc = fmaf(arow[e], att_mat[e * D_DIM + d], acc);
    g_AM[k * D_DIM + d] = acc;
}

// ---------------------------------------------------------------------------
// Kernel 2: per-candidate fused pipeline.
// grid = 256 (one block per candidate), block = 256 threads.
// ---------------------------------------------------------------------------
#define SB_STRIDE 129
#define SMEM_FLOATS (8192 + 64*SB_STRIDE + 4*64 + 2*128 + 4)

__global__ void cand_kernel(const float* __restrict__ table,
                            const float* __restrict__ str_t1,
                            const float* __restrict__ str_t2s,
                            const float* __restrict__ W,     // W_bi[0]: [128,128]
                            const float* __restrict__ b_bi,
                            const int* __restrict__ t2_ctx,
                            float* __restrict__ out) {
    extern __shared__ float sm[];
    float* sAM    = sm;                       // 8192
    float* sB     = sAM + K_CTX * D_DIM;      // 64*129
    float* rowsum = sB + K_CTX * SB_STRIDE;   // 64
    float* colsum = rowsum + K_CTX;           // 64
    float* rows_w = colsum + K_CTX;           // 64
    float* cols_w = rows_w + K_CTX;           // 64
    float* newA   = cols_w + K_CTX;           // 128
    float* newB   = newA + D_DIM;             // 128
    float* scal   = newB + D_DIM;             // 4

    const int c   = blockIdx.x;
    const int tid = threadIdx.x;

    // --- zero accumulators ---
    if (tid < K_CTX) { rowsum[tid] = 0.f; colsum[tid] = 0.f; }
    if (tid < 4) scal[tid] = 0.f;
    __syncthreads();

    // --- stage AM into smem (shared across candidates, L2-hot) ---
    for (int i = tid; i < K_CTX * D_DIM; i += 256)
        sAM[i] = g_AM[i];

    // --- gather B rows: 64 random table rows, coalesced within each row ---
    const int* ctx = t2_ctx + c * K_CTX;
    for (int i = tid; i < K_CTX * D_DIM; i += 256) {
        int m = i >> 7;
        int d = i & 127;
        sB[m * SB_STRIDE + d] = table[(long long)ctx[m] * D_DIM + d];
    }

    // --- string-branch cosine partials (overlaps with gather latency) ---
    {
        float pd = 0.f, p1 = 0.f, p2 = 0.f;
        for (int j = tid; j < DS; j += 256) {
            float x1 = str_t1[j];
            float x2 = str_t2s[c * DS + j];
            pd = fmaf(x1, x2, pd);
            p1 = fmaf(x1, x1, p1);
            p2 = fmaf(x2, x2, p2);
        }
#pragma unroll
        for (int off = 16; off; off >>= 1) {
            pd += __shfl_down_sync(0xffffffffu, pd, off);
            p1 += __shfl_down_sync(0xffffffffu, p1, off);
            p2 += __shfl_down_sync(0xffffffffu, p2, off);
        }
        if ((tid & 31) == 0) {
            atomicAdd(&scal[0], pd);
            atomicAdd(&scal[1], p1);
            atomicAdd(&scal[2], p2);
        }
    }
    __syncthreads();

    // --- sim = tanh(AM @ B^T): 4x4 register tile per thread, never stored ---
    {
        const int tr = tid >> 4;          // 0..15 -> k tile
        const int tc = tid & 15;          // 0..15 -> m tile
        const float* amp = sAM + tr * 4 * D_DIM;
        const float* bp  = sB  + tc * 4 * SB_STRIDE;

        float acc00 = 0, acc01 = 0, acc02 = 0, acc03 = 0;
        float acc10 = 0, acc11 = 0, acc12 = 0, acc13 = 0;
        float acc20 = 0, acc21 = 0, acc22 = 0, acc23 = 0;
        float acc30 = 0, acc31 = 0, acc32 = 0, acc33 = 0;

#pragma unroll 4
        for (int j = 0; j < D_DIM; j++) {
            float a0 = amp[j];
            float a1 = amp[D_DIM + j];
            float a2 = amp[2 * D_DIM + j];
            float a3 = amp[3 * D_DIM + j];
            float b0 = bp[j];
            float b1 = bp[SB_STRIDE + j];
            float b2 = bp[2 * SB_STRIDE + j];
            float b3 = bp[3 * SB_STRIDE + j];
            acc00 = fmaf(a0, b0, acc00); acc01 = fmaf(a0, b1, acc01);
            acc02 = fmaf(a0, b2, acc02); acc03 = fmaf(a0, b3, acc03);
            acc10 = fmaf(a1, b0, acc10); acc11 = fmaf(a1, b1, acc11);
            acc12 = fmaf(a1, b2, acc12); acc13 = fmaf(a1, b3, acc13);
            acc20 = fmaf(a2, b0, acc20); acc21 = fmaf(a2, b1, acc21);
            acc22 = fmaf(a2, b2, acc22); acc23 = fmaf(a2, b3, acc23);
            acc30 = fmaf(a3, b0, acc30); acc31 = fmaf(a3, b1, acc31);
            acc32 = fmaf(a3, b2, acc32); acc33 = fmaf(a3, b3, acc33);
        }

        float s00 = tanhf(acc00), s01 = tanhf(acc01), s02 = tanhf(acc02), s03 = tanhf(acc03);
        float s10 = tanhf(acc10), s11 = tanhf(acc11), s12 = tanhf(acc12), s13 = tanhf(acc13);
        float s20 = tanhf(acc20), s21 = tanhf(acc21), s22 = tanhf(acc22), s23 = tanhf(acc23);
        float s30 = tanhf(acc30), s31 = tanhf(acc31), s32 = tanhf(acc32), s33 = tanhf(acc33);

        // row partial sums (over m) and col partial sums (over k)
        atomicAdd(&rowsum[tr * 4 + 0], s00 + s01 + s02 + s03);
        atomicAdd(&rowsum[tr * 4 + 1], s10 + s11 + s12 + s13);
        atomicAdd(&rowsum[tr * 4 + 2], s20 + s21 + s22 + s23);
        atomicAdd(&rowsum[tr * 4 + 3], s30 + s31 + s32 + s33);
        atomicAdd(&colsum[tc * 4 + 0], s00 + s10 + s20 + s30);
        atomicAdd(&colsum[tc * 4 + 1], s01 + s11 + s21 + s31);
        atomicAdd(&colsum[tc * 4 + 2], s02 + s12 + s22 + s32);
        atomicAdd(&colsum[tc * 4 + 3], s03 + s13 + s23 + s33);
    }
    __syncthreads();

    // --- softmax over 64 values: warp 0 -> rows, warp 1 -> cols ---
    if (tid < 64) {
        const float* src = (tid < 32) ? rowsum : colsum;
        float* dst       = (tid < 32) ? rows_w : cols_w;
        int l = tid & 31;
        float v0 = src[l]      * (1.f / 64.f);
        float v1 = src[l + 32] * (1.f / 64.f);
        float mx = fmaxf(v0, v1);
#pragma unroll
        for (int off = 16; off; off >>= 1)
            mx = fmaxf(mx, __shfl_xor_sync(0xffffffffu, mx, off));
        float e0 = __expf(v0 - mx);
        float e1 = __expf(v1 - mx);
        float s = e0 + e1;
#pragma unroll
        for (int off = 16; off; off >>= 1)
            s += __shfl_xor_sync(0xffffffffu, s, off);
        float inv = 1.f / s;
        dst[l]      = e0 * inv;
        dst[l + 32] = e1 * inv;
    }
    __syncthreads();

    // --- new_A = rows @ A (A from gmem, L2-hot), new_B = cols @ B (smem) ---
    if (tid < D_DIM) {
        float na = 0.f, nb = 0.f;
#pragma unroll 8
        for (int k = 0; k < K_CTX; k++) {
            na = fmaf(rows_w[k], g_A[k * D_DIM + tid], na);
            nb = fmaf(cols_w[k], sB[k * SB_STRIDE + tid], nb);
        }
        newA[tid] = na;
        newB[tid] = nb;
    }
    __syncthreads();

    // --- con = newA @ W @ newB + b : s1[e] = sum_d newA[d] W[d,e] (coalesced) ---
    if (tid < D_DIM) {
        float s1 = 0.f;
#pragma unroll 8
        for (int d = 0; d < D_DIM; d++)
            s1 = fmaf(newA[d], W[d * D_DIM + tid], s1);
        float pc = s1 * newB[tid];
#pragma unroll
        for (int off = 16; off; off >>= 1)
            pc += __shfl_down_sync(0xffffffffu, pc, off);
        if ((tid & 31) == 0) atomicAdd(&scal[3], pc);
    }
    __syncthreads();

    if (tid == 0) {
        float n1 = fmaxf(sqrtf(scal[1]), EPS);
        float n2 = fmaxf(sqrtf(scal[2]), EPS);
        float str_score = scal[0] / (n1 * n2);
        float con_score = scal[3] + b_bi[0];
        out[c] = 0.5f * str_score + 0.5f * con_score;
    }
}

// ---------------------------------------------------------------------------
extern "C" void kernel_launch(void* const* d_in, const int* in_sizes, int n_in,
                              void* d_out, int out_size) {
    const float* table   = (const float*)d_in[0];
    const float* str_t1  = (const float*)d_in[1];
    const float* str_t2s = (const float*)d_in[2];
    const float* att_mat = (const float*)d_in[3];
    const float* W_bi    = (const float*)d_in[4];
    const float* b_bi    = (const float*)d_in[5];
    const int*   t1_ctx  = (const int*)d_in[6];
    const int*   t2_ctx  = (const int*)d_in[7];
    float* out = (float*)d_out;

    cudaFuncSetAttribute(cand_kernel,
                         cudaFuncAttributeMaxDynamicSharedMemorySize,
                         SMEM_FLOATS * sizeof(float));

    prep_kernel<<<K_CTX, D_DIM>>>(table, att_mat, t1_ctx);
    cand_kernel<<<C_CAND, 256, SMEM_FLOATS * sizeof(float)>>>(
        table, str_t1, str_t2s, W_bi, b_bi, t2_ctx, out);
}